// round 1
// baseline (speedup 1.0000x reference)
#include <cuda_runtime.h>
#include <math.h>

// Problem constants
#define BSZ  256      // batch
#define NN   1024     // ECNUM = CA1NUM = CA3NUM
#define TT   100      // TRACKLENGTH
#define NBLK 128
#define NTHR 256
#define TM   32       // tile rows
#define TN   64       // tile cols
#define KC   32       // k-chunk

// Output layout (floats): actCell(256*2), ec3his(100*1024), ec5his, ca1his,
// ec3(256*1024), ec5, ca1
#define O_ACT 0
#define O_E3H 512
#define O_E5H (512 + 102400)
#define O_C1H (512 + 2*102400)
#define O_E3F (512 + 3*102400)
#define O_E5F (O_E3F + 262144)
#define O_C1F (O_E5F + 262144)

// Persistent device state (allowed: __device__ globals, no allocation)
__device__ float g_ec3[BSZ*NN];
__device__ float g_ec5[BSZ*NN];
__device__ float g_ca1[BSZ*NN];
__device__ float g_ca3[TT*NN];
__device__ float g_drive[TT*NN];
__device__ unsigned g_arrive = 0;   // monotonic arrival counter (wrap-safe compares)

__device__ __forceinline__ float sigm(float x) { return 1.0f / (1.0f + expf(-x)); }

// Grid-wide barrier: monotone counter, no reset races. All NBLK blocks are
// resident (128 <= 148 SMs, 1 block/SM), so spinning is deadlock-free.
__device__ __forceinline__ void grid_sync(unsigned base, unsigned idx) {
    __syncthreads();
    if (threadIdx.x == 0) {
        __threadfence();                       // release my global writes
        atomicAdd(&g_arrive, 1u);
        const unsigned goal = idx * (unsigned)NBLK;
        while ((*(volatile unsigned*)&g_arrive) - base < goal) { }
        __threadfence();                       // acquire others' writes
    }
    __syncthreads();
}

// Tiled fp32 GEMM accumulate for one 32x64 output tile.
// A: M x 1024 row-major (M = 256 or 100, rows >= M read as zero)
// B: 1024 x 1024 row-major
// acc[2][4]: thread (mi,ni) owns rows m0+2*mi+{0,1}, cols n0+4*ni+{0..3}
__device__ __forceinline__ void gemm_acc(
    const float* __restrict__ A, const float* __restrict__ B,
    int M, int m0, int n0, float (&acc)[2][4], float* As, float* Bs)
{
    const int tid  = threadIdx.x;
    const int la_i = tid >> 3, la_j4 = tid & 7;    // A loader: row-in-tile, k-float4
    const int lb_j = tid >> 4, lb_c4 = tid & 15;   // B loader: k-row, col-float4
    const int mi   = tid >> 4, ni = tid & 15;

#pragma unroll
    for (int i = 0; i < 2; i++)
#pragma unroll
        for (int j = 0; j < 4; j++) acc[i][j] = 0.0f;

    const int  gm = m0 + la_i;
    const bool av = (gm < M);
    const float* Ab = A + gm * NN;

    float4 pa  = av ? *(const float4*)(Ab + la_j4 * 4) : make_float4(0.f, 0.f, 0.f, 0.f);
    float4 pb0 = *(const float4*)(B + lb_j * NN + n0 + lb_c4 * 4);
    float4 pb1 = *(const float4*)(B + (lb_j + 16) * NN + n0 + lb_c4 * 4);

    for (int kk = 0; kk < NN; kk += KC) {
        __syncthreads();   // previous chunk's compute done before overwrite
        // As stored transposed [k][m] with pad-33 (conflict-free stores/loads)
        As[(la_j4 * 4 + 0) * 33 + la_i] = pa.x;
        As[(la_j4 * 4 + 1) * 33 + la_i] = pa.y;
        As[(la_j4 * 4 + 2) * 33 + la_i] = pa.z;
        As[(la_j4 * 4 + 3) * 33 + la_i] = pa.w;
        *(float4*)(Bs + lb_j * TN + lb_c4 * 4)        = pb0;
        *(float4*)(Bs + (lb_j + 16) * TN + lb_c4 * 4) = pb1;
        __syncthreads();

        const int k2 = kk + KC;
        if (k2 < NN) {     // register prefetch of next chunk hides L2 latency
            pa  = av ? *(const float4*)(Ab + k2 + la_j4 * 4) : make_float4(0.f, 0.f, 0.f, 0.f);
            pb0 = *(const float4*)(B + (k2 + lb_j) * NN + n0 + lb_c4 * 4);
            pb1 = *(const float4*)(B + (k2 + lb_j + 16) * NN + n0 + lb_c4 * 4);
        }

#pragma unroll
        for (int k = 0; k < KC; k++) {
            const float  a0 = As[k * 33 + mi * 2];
            const float  a1 = As[k * 33 + mi * 2 + 1];
            const float4 bv = *(const float4*)(Bs + k * TN + ni * 4);
            acc[0][0] = fmaf(a0, bv.x, acc[0][0]);
            acc[0][1] = fmaf(a0, bv.y, acc[0][1]);
            acc[0][2] = fmaf(a0, bv.z, acc[0][2]);
            acc[0][3] = fmaf(a0, bv.w, acc[0][3]);
            acc[1][0] = fmaf(a1, bv.x, acc[1][0]);
            acc[1][1] = fmaf(a1, bv.y, acc[1][1]);
            acc[1][2] = fmaf(a1, bv.z, acc[1][2]);
            acc[1][3] = fmaf(a1, bv.w, acc[1][3]);
        }
    }
}

extern "C" __global__ void __launch_bounds__(NTHR, 1) rnn_kernel(
    const unsigned* __restrict__ cue,      // (256,2,1024) bool stored 4-byte; nonzero test
    const float* __restrict__ ec3_last,
    const float* __restrict__ ec5_last,
    const float* __restrict__ ca1bias,
    const float* __restrict__ wca3ca1,
    const float* __restrict__ wec3ca1,
    const float* __restrict__ wca1ec5,
    const float* __restrict__ wca1act,
    const float* __restrict__ actbias,
    float* __restrict__ out)
{
    __shared__ float As[KC * 33];
    __shared__ float Bs[KC * TN];
    __shared__ unsigned s_base;

    const int tid = threadIdx.x;
    const int b   = blockIdx.x;

    if (tid == 0) s_base = *(volatile unsigned*)&g_arrive;
    __syncthreads();
    const unsigned base = s_base;
    unsigned bar = 0;

    // ---- phase 0: copy recurrent state, compute CA3 place fields ----
    {
        const int stride = NBLK * NTHR;
        for (int i = b * NTHR + tid; i < BSZ * NN; i += stride) {
            g_ec3[i] = ec3_last[i];
            g_ec5[i] = ec5_last[i];
        }
        for (int i = b * NTHR + tid; i < TT * NN; i += stride) {
            const int   t = i >> 10;
            const int   k = i & 1023;
            const float c = (100.0f / 1023.0f) * (float)k;   // linspace(0,100,1024)
            const float d = c - (float)t;
            g_ca3[i] = expf(-d * d * 0.02f);                 // /(sigma^2)/2 = /50
        }
    }
    grid_sync(base, ++bar);

    const int m0 = (b >> 4) * TM;
    const int n0 = (b & 15) * TN;
    const int mi = tid >> 4, ni = tid & 15;
    const int em = mi * 2, en = ni * 4;

    // ---- phase 1: drive = ca3all @ wca3ca1  (100x1024x1024), blocks 0..63 ----
    if (b < 64) {
        float acc[2][4];
        gemm_acc(g_ca3, wca3ca1, TT, m0, n0, acc, As, Bs);
#pragma unroll
        for (int i = 0; i < 2; i++) {
            const int m = m0 + em + i;
            if (m < TT) {
#pragma unroll
                for (int j = 0; j < 4; j++) g_drive[m * NN + n0 + en + j] = acc[i][j];
            }
        }
    }
    grid_sync(base, ++bar);

    // ---- recurrent scan: 100 steps, 2 GEMMs each ----
    for (int t = 0; t < TT; t++) {
        float acc[2][4];

        // GEMM1: tmp = ec3 @ wec3ca1 ; ca1 = relu(drive*(1+sigm(tmp)) - bias)
        gemm_acc(g_ec3, wec3ca1, BSZ, m0, n0, acc, As, Bs);
        const float* drow = g_drive + t * NN;
#pragma unroll
        for (int i = 0; i < 2; i++) {
            const int m = m0 + em + i;
#pragma unroll
            for (int j = 0; j < 4; j++) {
                const int n = n0 + en + j;
                float v = drow[n] * (1.0f + sigm(acc[i][j])) - ca1bias[n];
                v = fmaxf(v, 0.0f);
                g_ca1[m * NN + n] = v;
                if (m == 0)      out[O_C1H + t * NN + n] = v;
                if (t == TT - 1) out[O_C1F + m * NN + n] = v;
            }
        }
        grid_sync(base, ++bar);

        // GEMM2: ec5 += ca1 @ wca1ec5 (10*TS = 1.0); squash; ec3 update + cue mask
        gemm_acc(g_ca1, wca1ec5, BSZ, m0, n0, acc, As, Bs);
#pragma unroll
        for (int i = 0; i < 2; i++) {
            const int m = m0 + em + i;
#pragma unroll
            for (int j = 0; j < 4; j++) {
                const int n   = n0 + en + j;
                const int idx = m * NN + n;
                float e5 = g_ec5[idx] + acc[i][j];
                e5 = 0.69f + 0.3f * sigm(4.0f * (e5 - 0.3f));
                float e3 = e5 * g_ec3[idx];
                // cueloc = 8*(s+2) -> t==16 uses cue[:,0,:], t==24 uses cue[:,1,:]
                if (t == 16 && cue[m * 2048 + n]        != 0u) e3 = 0.4f * e3 + 0.6f;
                if (t == 24 && cue[m * 2048 + 1024 + n] != 0u) e3 = 0.4f * e3 + 0.6f;
                g_ec5[idx] = e5;
                g_ec3[idx] = e3;
                if (m == 0) {
                    out[O_E3H + t * NN + n] = e3;
                    out[O_E5H + t * NN + n] = e5;
                }
                if (t == TT - 1) {
                    out[O_E3F + idx] = e3;
                    out[O_E5F + idx] = e5;
                }
            }
        }
        grid_sync(base, ++bar);
    }

    // ---- actCell = ca1_final @ wca1act + actbias  (256x2, K=1024) ----
    {
        const int w = tid >> 5, lane = tid & 31;
        if (w < 4) {
            const int r = 2 * b + (w >> 1);
            const int a = w & 1;
            float s = 0.0f;
            for (int k = lane; k < NN; k += 32)
                s = fmaf(g_ca1[r * NN + k], wca1act[k * 2 + a], s);
#pragma unroll
            for (int off = 16; off; off >>= 1)
                s += __shfl_xor_sync(0xffffffffu, s, off);
            if (lane == 0) out[O_ACT + r * 2 + a] = s + actbias[a];
        }
    }
}

extern "C" void kernel_launch(void* const* d_in, const int* in_sizes, int n_in,
                              void* d_out, int out_size)
{
    // metadata order: cue, ec3_last, ec5_last, ca1_last, ca1bias, wca3ca1,
    //                 wec3ca1, wca1ec5, wca1act, actbias
    rnn_kernel<<<NBLK, NTHR>>>(
        (const unsigned*)d_in[0],
        (const float*)d_in[1],
        (const float*)d_in[2],
        (const float*)d_in[4],
        (const float*)d_in[5],
        (const float*)d_in[6],
        (const float*)d_in[7],
        (const float*)d_in[8],
        (const float*)d_in[9],
        (float*)d_out);
}

// round 2
// speedup vs baseline: 1.0938x; 1.0938x over previous
#include <cuda_runtime.h>
#include <math.h>

// Problem constants
#define BSZ  256      // batch
#define NN   1024     // ECNUM = CA1NUM = CA3NUM
#define TT   100      // TRACKLENGTH
#define NBLK 128
#define NTHR 128
#define TM   32       // tile rows
#define TN   64       // tile cols
#define KC   32       // k-chunk
#define NCH  (NN / KC)

// Output layout (floats): actCell(256*2), ec3his(100*1024), ec5his, ca1his,
// ec3(256*1024), ec5, ca1
#define O_ACT 0
#define O_E3H 512
#define O_E5H (512 + 102400)
#define O_C1H (512 + 2*102400)
#define O_E3F (512 + 3*102400)
#define O_E5F (O_E3F + 262144)
#define O_C1F (O_E5F + 262144)

// Persistent device state
__device__ float g_ec3[BSZ*NN];
__device__ float g_ec5[BSZ*NN];
__device__ float g_ca1[BSZ*NN];
__device__ float g_ca3[TT*NN];
__device__ float g_drive[TT*NN];
__device__ unsigned g_arrive = 0;   // monotonic arrival counter

__device__ __forceinline__ float sigm(float x) {
    return __fdividef(1.0f, 1.0f + __expf(-x));
}

// Grid-wide barrier: monotone counter. All NBLK blocks resident (128 <= 148 SMs).
__device__ __forceinline__ void grid_sync(unsigned base, unsigned idx) {
    __syncthreads();
    if (threadIdx.x == 0) {
        __threadfence();
        atomicAdd(&g_arrive, 1u);
        const unsigned goal = idx * (unsigned)NBLK;
        while ((*(volatile unsigned*)&g_arrive) - base < goal) { }
        __threadfence();
    }
    __syncthreads();
}

// Tiled fp32 GEMM for one 32x64 tile, 128 threads, 4x4 micro-tile,
// double-buffered smem (one __syncthreads per K-chunk).
// A: M x 1024 row-major (rows >= M read as zero). B: 1024 x 1024 row-major.
// Thread (mi=tid>>4, ni=tid&15) owns rows m0+mi*4+{0..3}, cols n0+ni*4+{0..3}.
__device__ __forceinline__ void gemm_acc(
    const float* __restrict__ A, const float* __restrict__ B,
    int M, int m0, int n0, float (&acc)[4][4], float* As, float* Bs)
{
    const int tid = threadIdx.x;
    const int am  = tid & 31, aj = tid >> 5;   // A loader: row-in-tile, k-quad
    const int bc  = tid & 15, bj = tid >> 4;   // B loader: col-quad, k-row
    const int mi  = tid >> 4, ni = tid & 15;

#pragma unroll
    for (int i = 0; i < 4; i++)
#pragma unroll
        for (int j = 0; j < 4; j++) acc[i][j] = 0.0f;

    const int  gm = m0 + am;
    const bool av = (gm < M);
    const float* Ap = A + gm * NN;
    const float* Bp = B + n0 + bc * 4;
    const float4 f40 = make_float4(0.f, 0.f, 0.f, 0.f);

    float4 ra0, ra1, rb0, rb1, rb2, rb3;
    // load chunk 0 into regs
    ra0 = av ? *(const float4*)(Ap + aj * 4)      : f40;
    ra1 = av ? *(const float4*)(Ap + 16 + aj * 4) : f40;
    rb0 = *(const float4*)(Bp + (bj +  0) * NN);
    rb1 = *(const float4*)(Bp + (bj +  8) * NN);
    rb2 = *(const float4*)(Bp + (bj + 16) * NN);
    rb3 = *(const float4*)(Bp + (bj + 24) * NN);

    for (int c = 0; c < NCH; c++) {
        const int cb = c & 1;
        float* Aw = As + cb * (KC * 32);
        float* Bw = Bs + cb * (KC * 64);
        // store current chunk (transposed A: [k][m])
        Aw[(aj * 4 + 0) * 32 + am] = ra0.x;
        Aw[(aj * 4 + 1) * 32 + am] = ra0.y;
        Aw[(aj * 4 + 2) * 32 + am] = ra0.z;
        Aw[(aj * 4 + 3) * 32 + am] = ra0.w;
        Aw[(16 + aj * 4 + 0) * 32 + am] = ra1.x;
        Aw[(16 + aj * 4 + 1) * 32 + am] = ra1.y;
        Aw[(16 + aj * 4 + 2) * 32 + am] = ra1.z;
        Aw[(16 + aj * 4 + 3) * 32 + am] = ra1.w;
        *(float4*)(Bw + (bj +  0) * TN + bc * 4) = rb0;
        *(float4*)(Bw + (bj +  8) * TN + bc * 4) = rb1;
        *(float4*)(Bw + (bj + 16) * TN + bc * 4) = rb2;
        *(float4*)(Bw + (bj + 24) * TN + bc * 4) = rb3;
        __syncthreads();

        const int kn = (c + 1) * KC;
        if (kn < NN) {   // prefetch next chunk; LDGs fly during compute below
            ra0 = av ? *(const float4*)(Ap + kn + aj * 4)      : f40;
            ra1 = av ? *(const float4*)(Ap + kn + 16 + aj * 4) : f40;
            rb0 = *(const float4*)(Bp + (kn + bj +  0) * NN);
            rb1 = *(const float4*)(Bp + (kn + bj +  8) * NN);
            rb2 = *(const float4*)(Bp + (kn + bj + 16) * NN);
            rb3 = *(const float4*)(Bp + (kn + bj + 24) * NN);
        }

        const float* Ab = As + cb * (KC * 32);
        const float* Bb = Bs + cb * (KC * 64);
#pragma unroll 8
        for (int k = 0; k < KC; k++) {
            const float4 a = *(const float4*)(Ab + k * 32 + mi * 4);
            const float4 b = *(const float4*)(Bb + k * 64 + ni * 4);
            acc[0][0] = fmaf(a.x, b.x, acc[0][0]);
            acc[0][1] = fmaf(a.x, b.y, acc[0][1]);
            acc[0][2] = fmaf(a.x, b.z, acc[0][2]);
            acc[0][3] = fmaf(a.x, b.w, acc[0][3]);
            acc[1][0] = fmaf(a.y, b.x, acc[1][0]);
            acc[1][1] = fmaf(a.y, b.y, acc[1][1]);
            acc[1][2] = fmaf(a.y, b.z, acc[1][2]);
            acc[1][3] = fmaf(a.y, b.w, acc[1][3]);
            acc[2][0] = fmaf(a.z, b.x, acc[2][0]);
            acc[2][1] = fmaf(a.z, b.y, acc[2][1]);
            acc[2][2] = fmaf(a.z, b.z, acc[2][2]);
            acc[2][3] = fmaf(a.z, b.w, acc[2][3]);
            acc[3][0] = fmaf(a.w, b.x, acc[3][0]);
            acc[3][1] = fmaf(a.w, b.y, acc[3][1]);
            acc[3][2] = fmaf(a.w, b.z, acc[3][2]);
            acc[3][3] = fmaf(a.w, b.w, acc[3][3]);
        }
        // NOTE: next iteration stores into buffer cb^1, which was last read in
        // iteration c-1; the __syncthreads above orders that. One sync/chunk.
    }
    __syncthreads();  // protect smem reuse by caller / next gemm
}

extern "C" __global__ void __launch_bounds__(NTHR, 1) rnn_kernel(
    const unsigned* __restrict__ cue,      // (256,2,1024) bool stored 4-byte
    const float* __restrict__ ec3_last,
    const float* __restrict__ ec5_last,
    const float* __restrict__ ca1bias,
    const float* __restrict__ wca3ca1,
    const float* __restrict__ wec3ca1,
    const float* __restrict__ wca1ec5,
    const float* __restrict__ wca1act,
    const float* __restrict__ actbias,
    float* __restrict__ out)
{
    __shared__ float As[2 * KC * 32];
    __shared__ float Bs[2 * KC * 64];
    __shared__ unsigned s_base;

    const int tid = threadIdx.x;
    const int b   = blockIdx.x;

    if (tid == 0) s_base = *(volatile unsigned*)&g_arrive;
    __syncthreads();
    const unsigned base = s_base;
    unsigned bar = 0;

    // ---- phase 0: copy state, compute CA3 place fields ----
    {
        const int stride = NBLK * NTHR;
        for (int i = b * NTHR + tid; i < BSZ * NN; i += stride) {
            g_ec3[i] = ec3_last[i];
            g_ec5[i] = ec5_last[i];
        }
        for (int i = b * NTHR + tid; i < TT * NN; i += stride) {
            const int   t = i >> 10;
            const int   k = i & 1023;
            const float c = (100.0f / 1023.0f) * (float)k;   // linspace(0,100,1024)
            const float d = c - (float)t;
            g_ca3[i] = expf(-d * d * 0.02f);
        }
    }
    grid_sync(base, ++bar);

    const int m0 = (b >> 4) * TM;
    const int n0 = (b & 15) * TN;
    const int mi = tid >> 4, ni = tid & 15;

    // ---- phase 1: drive = ca3all @ wca3ca1 (100x1024x1024), blocks 0..63 ----
    if (b < 64) {
        float acc[4][4];
        gemm_acc(g_ca3, wca3ca1, TT, m0, n0, acc, As, Bs);
#pragma unroll
        for (int i = 0; i < 4; i++) {
            const int m = m0 + mi * 4 + i;
            if (m < TT) {
#pragma unroll
                for (int j = 0; j < 4; j++)
                    g_drive[m * NN + n0 + ni * 4 + j] = acc[i][j];
            }
        }
    }
    grid_sync(base, ++bar);

    // ---- recurrent scan ----
    for (int t = 0; t < TT; t++) {
        float acc[4][4];

        // GEMM1: tmp = ec3 @ wec3ca1 ; ca1 = relu(drive*(1+sigm(tmp)) - bias)
        gemm_acc(g_ec3, wec3ca1, BSZ, m0, n0, acc, As, Bs);
        const float* drow = g_drive + t * NN;
#pragma unroll
        for (int i = 0; i < 4; i++) {
            const int m = m0 + mi * 4 + i;
#pragma unroll
            for (int j = 0; j < 4; j++) {
                const int n = n0 + ni * 4 + j;
                float v = drow[n] * (1.0f + sigm(acc[i][j])) - ca1bias[n];
                v = fmaxf(v, 0.0f);
                g_ca1[m * NN + n] = v;
                if (m == 0)      out[O_C1H + t * NN + n] = v;
                if (t == TT - 1) out[O_C1F + m * NN + n] = v;
            }
        }
        grid_sync(base, ++bar);

        // GEMM2: ec5 += ca1 @ wca1ec5; squash; ec3 update + cue mask
        gemm_acc(g_ca1, wca1ec5, BSZ, m0, n0, acc, As, Bs);
#pragma unroll
        for (int i = 0; i < 4; i++) {
            const int m = m0 + mi * 4 + i;
#pragma unroll
            for (int j = 0; j < 4; j++) {
                const int n   = n0 + ni * 4 + j;
                const int idx = m * NN + n;
                float e5 = g_ec5[idx] + acc[i][j];
                e5 = 0.69f + 0.3f * sigm(4.0f * (e5 - 0.3f));
                float e3 = e5 * g_ec3[idx];
                // cueloc = 8*(s+2): t==16 -> cue[:,0,:], t==24 -> cue[:,1,:]
                if (t == 16 && cue[m * 2048 + n]        != 0u) e3 = 0.4f * e3 + 0.6f;
                if (t == 24 && cue[m * 2048 + 1024 + n] != 0u) e3 = 0.4f * e3 + 0.6f;
                g_ec5[idx] = e5;
                g_ec3[idx] = e3;
                if (m == 0) {
                    out[O_E3H + t * NN + n] = e3;
                    out[O_E5H + t * NN + n] = e5;
                }
                if (t == TT - 1) {
                    out[O_E3F + idx] = e3;
                    out[O_E5F + idx] = e5;
                }
            }
        }
        grid_sync(base, ++bar);
    }

    // ---- actCell = ca1_final @ wca1act + actbias (256x2, K=1024) ----
    {
        const int w = tid >> 5, lane = tid & 31;
        const int r = 2 * b + (w >> 1);
        const int a = w & 1;
        float s = 0.0f;
        for (int k = lane; k < NN; k += 32)
            s = fmaf(g_ca1[r * NN + k], wca1act[k * 2 + a], s);
#pragma unroll
        for (int off = 16; off; off >>= 1)
            s += __shfl_xor_sync(0xffffffffu, s, off);
        if (lane == 0) out[O_ACT + r * 2 + a] = s + actbias[a];
    }
}

extern "C" void kernel_launch(void* const* d_in, const int* in_sizes, int n_in,
                              void* d_out, int out_size)
{
    // metadata order: cue, ec3_last, ec5_last, ca1_last, ca1bias, wca3ca1,
    //                 wec3ca1, wca1ec5, wca1act, actbias
    rnn_kernel<<<NBLK, NTHR>>>(
        (const unsigned*)d_in[0],
        (const float*)d_in[1],
        (const float*)d_in[2],
        (const float*)d_in[4],
        (const float*)d_in[5],
        (const float*)d_in[6],
        (const float*)d_in[7],
        (const float*)d_in[8],
        (const float*)d_in[9],
        (float*)d_out);
}